// round 1
// baseline (speedup 1.0000x reference)
#include <cuda_runtime.h>
#include <cuda_bf16.h>
#include <float.h>
#include <math.h>

#define K_TOPICS 100
#define VOCAB    8192
#define TOPN     20

// ---- persistent device scratch (no allocations allowed) ----
__device__ int   g_topidx[K_TOPICS * TOPN];
__device__ float g_pval[K_TOPICS * TOPN];
__device__ float g_rowmax[K_TOPICS];
__device__ float g_invdenom[K_TOPICS];
__device__ int   g_colsum[VOCAB];
__device__ float g_pos;
__device__ float g_neg;

// ----------------------------------------------------------------------------
// Kernel 0: zero the scratch that accumulates across a launch
// ----------------------------------------------------------------------------
__global__ void zero_kernel() {
    int i = blockIdx.x * blockDim.x + threadIdx.x;
    if (i < VOCAB) g_colsum[i] = 0;
    if (i == 0) { g_pos = 0.0f; g_neg = 0.0f; }
}

// ----------------------------------------------------------------------------
// Kernel A: per-topic full-row softmax stats + exact top-20 + p + colsum
// grid = 100 blocks, 256 threads
// ----------------------------------------------------------------------------
__global__ void __launch_bounds__(256) topk_kernel(const float* __restrict__ beta) {
    const int t   = blockIdx.x;
    const int tid = threadIdx.x;

    __shared__ float s[VOCAB];        // working copy of the beta row (32 KB)
    __shared__ float s_val[256];
    __shared__ int   s_ind[256];
    __shared__ float s_bcast;
    __shared__ float tv[TOPN];
    __shared__ int   ti[TOPN];

    const float* row = beta + (size_t)t * VOCAB;
    for (int i = tid; i < VOCAB; i += 256) s[i] = row[i];
    __syncthreads();

    // ---- full-row max ----
    float m = -FLT_MAX;
    for (int i = tid; i < VOCAB; i += 256) m = fmaxf(m, s[i]);
    s_val[tid] = m;
    __syncthreads();
    for (int off = 128; off > 0; off >>= 1) {
        if (tid < off) s_val[tid] = fmaxf(s_val[tid], s_val[tid + off]);
        __syncthreads();
    }
    if (tid == 0) s_bcast = s_val[0];
    __syncthreads();
    const float rowmax = s_bcast;

    // ---- full-row sum of exp(beta - max) ----
    float z = 0.0f;
    for (int i = tid; i < VOCAB; i += 256) z += __expf(s[i] - rowmax);
    s_val[tid] = z;
    __syncthreads();
    for (int off = 128; off > 0; off >>= 1) {
        if (tid < off) s_val[tid] += s_val[tid + off];
        __syncthreads();
    }
    if (tid == 0) {
        g_rowmax[t]   = rowmax;
        g_invdenom[t] = 1.0f / s_val[0];
    }
    __syncthreads();

    // ---- iterative top-20 (exact argmax; destroys s) ----
    for (int it = 0; it < TOPN; ++it) {
        float bv = -FLT_MAX; int bi = 0;
        for (int i = tid; i < VOCAB; i += 256) {
            float v = s[i];
            if (v > bv) { bv = v; bi = i; }
        }
        s_val[tid] = bv; s_ind[tid] = bi;
        __syncthreads();
        for (int off = 128; off > 0; off >>= 1) {
            if (tid < off && s_val[tid + off] > s_val[tid]) {
                s_val[tid] = s_val[tid + off];
                s_ind[tid] = s_ind[tid + off];
            }
            __syncthreads();
        }
        if (tid == 0) {
            tv[it] = s_val[0];
            ti[it] = s_ind[0];
            s[s_ind[0]] = -FLT_MAX;   // knock out for next pass
        }
        __syncthreads();
    }

    // ---- p = softmax over the 20 top values (non-topk underflow to exact 0) ----
    if (tid == 0) {
        float mt = tv[0];                 // tv[0] is the global max
        float zz = 0.0f;
        for (int j = 0; j < TOPN; ++j) zz += expf(tv[j] - mt);
        float inv = 1.0f / zz;
        for (int j = 0; j < TOPN; ++j) {
            g_pval[t * TOPN + j]   = expf(tv[j] - mt) * inv;
            g_topidx[t * TOPN + j] = ti[j];
            atomicAdd(&g_colsum[ti[j]], 1);
        }
    }
}

// ----------------------------------------------------------------------------
// Kernel B: per-topic M = p @ W (20 rows), row min/max, masked loss reduction
// grid = 100 blocks, 1024 threads. Each thread owns 8 columns as 2 float4s:
//   cols [4*tid, 4*tid+4)  and  [4*(tid+1024), 4*(tid+1024)+4)
// ----------------------------------------------------------------------------
__global__ void __launch_bounds__(1024) loss_kernel(const float* __restrict__ beta,
                                                    const float* __restrict__ W) {
    const int t   = blockIdx.x;
    const int tid = threadIdx.x;

    __shared__ int   s_idx[TOPN];
    __shared__ float s_p[TOPN];
    __shared__ float s_red[32];
    __shared__ float s_mnb, s_mxb;

    if (tid < TOPN) {
        s_idx[tid] = g_topidx[t * TOPN + tid];
        s_p[tid]   = g_pval[t * TOPN + tid];
    }
    __syncthreads();

    const float4* __restrict__ W4 = (const float4*)W;

    float4 acc0 = make_float4(0.f, 0.f, 0.f, 0.f);
    float4 acc1 = make_float4(0.f, 0.f, 0.f, 0.f);

    #pragma unroll 5
    for (int j = 0; j < TOPN; ++j) {
        const size_t base = (size_t)s_idx[j] * (VOCAB / 4);
        const float  w    = s_p[j];
        float4 a = __ldg(&W4[base + tid]);
        float4 b = __ldg(&W4[base + tid + 1024]);
        acc0.x += w * a.x; acc0.y += w * a.y; acc0.z += w * a.z; acc0.w += w * a.w;
        acc1.x += w * b.x; acc1.y += w * b.y; acc1.z += w * b.z; acc1.w += w * b.w;
    }

    // ---- block min/max of M over this row ----
    float mn = fminf(fminf(fminf(acc0.x, acc0.y), fminf(acc0.z, acc0.w)),
                     fminf(fminf(acc1.x, acc1.y), fminf(acc1.z, acc1.w)));
    float mx = fmaxf(fmaxf(fmaxf(acc0.x, acc0.y), fmaxf(acc0.z, acc0.w)),
                     fmaxf(fmaxf(acc1.x, acc1.y), fmaxf(acc1.z, acc1.w)));
    for (int o = 16; o > 0; o >>= 1) {
        mn = fminf(mn, __shfl_xor_sync(0xffffffffu, mn, o));
        mx = fmaxf(mx, __shfl_xor_sync(0xffffffffu, mx, o));
    }
    if ((tid & 31) == 0) s_red[tid >> 5] = mn;
    __syncthreads();
    if (tid < 32) {
        float v = s_red[tid];
        for (int o = 16; o > 0; o >>= 1) v = fminf(v, __shfl_xor_sync(0xffffffffu, v, o));
        if (tid == 0) s_mnb = v;
    }
    __syncthreads();
    if ((tid & 31) == 0) s_red[tid >> 5] = mx;
    __syncthreads();
    if (tid < 32) {
        float v = s_red[tid];
        for (int o = 16; o > 0; o >>= 1) v = fmaxf(v, __shfl_xor_sync(0xffffffffu, v, o));
        if (tid == 0) s_mxb = v;
    }
    __syncthreads();
    const float mmin = s_mnb;
    const float inv  = 1.0f / (s_mxb - mmin);

    // ---- per-column loss, split by diversity mask Md ----
    const float rm = g_rowmax[t];
    const float id = g_invdenom[t];
    const float4* __restrict__ beta4 = (const float4*)(beta + (size_t)t * VOCAB);
    const int4*   __restrict__ cs4   = (const int4*)g_colsum;

    float pos = 0.0f, neg = 0.0f;

    #pragma unroll
    for (int half = 0; half < 2; ++half) {
        const int v4   = tid + half * 1024;
        float4 bvec    = beta4[v4];
        int4   cvec    = cs4[v4];
        float4 Mvec    = half ? acc1 : acc0;

        float bb[4] = { bvec.x, bvec.y, bvec.z, bvec.w };
        int   cc[4] = { cvec.x, cvec.y, cvec.z, cvec.w };
        float MM[4] = { Mvec.x, Mvec.y, Mvec.z, Mvec.w };

        #pragma unroll
        for (int k = 0; k < 4; ++k) {
            const int col = v4 * 4 + k;
            int inTop = 0;
            #pragma unroll
            for (int j = 0; j < TOPN; ++j) inTop |= (s_idx[j] == col);
            const float sft = expf(bb[k] - rm) * id;      // full softmax(beta)
            const float wc  = 1.0f - (MM[k] - mmin) * inv;
            const float l   = 100.0f * sft * sft * wc;
            const bool  md  = (cc[k] - inTop) > 0;
            if (md) pos += l; else neg += l;
        }
    }

    // ---- block reduce pos/neg, one atomic pair per block ----
    for (int o = 16; o > 0; o >>= 1) {
        pos += __shfl_xor_sync(0xffffffffu, pos, o);
        neg += __shfl_xor_sync(0xffffffffu, neg, o);
    }
    __syncthreads();              // s_red reuse
    if ((tid & 31) == 0) s_red[tid >> 5] = pos;
    __syncthreads();
    if (tid < 32) {
        float v = s_red[tid];
        for (int o = 16; o > 0; o >>= 1) v += __shfl_xor_sync(0xffffffffu, v, o);
        if (tid == 0) atomicAdd(&g_pos, v);
    }
    __syncthreads();
    if ((tid & 31) == 0) s_red[tid >> 5] = neg;
    __syncthreads();
    if (tid < 32) {
        float v = s_red[tid];
        for (int o = 16; o > 0; o >>= 1) v += __shfl_xor_sync(0xffffffffu, v, o);
        if (tid == 0) atomicAdd(&g_neg, v);
    }
}

// ----------------------------------------------------------------------------
// Kernel C: finalize scalar
// ----------------------------------------------------------------------------
__global__ void finalize_kernel(const int* __restrict__ epoch_ptr,
                                float* __restrict__ out) {
    const int   epoch        = epoch_ptr[0];
    const int   warmup       = 100;                 // 0.5 * 200
    const float lambda_delta = 100.0f / (float)warmup;  // 1.0
    const float lambda_a     = (epoch < warmup) ? (float)epoch * lambda_delta : 100.0f;
    const float total = (g_pos * 0.7f + g_neg * 0.3f) * 2.0f;
    out[0] = lambda_a * total;
}

// ----------------------------------------------------------------------------
extern "C" void kernel_launch(void* const* d_in, const int* in_sizes, int n_in,
                              void* d_out, int out_size) {
    // Match inputs by element count (robust to metadata ordering):
    //   beta: 100*8192 = 819200, W: 8192*8192 = 67108864, epoch: 1
    const float* beta  = nullptr;
    const float* W     = nullptr;
    const int*   epoch = nullptr;
    for (int i = 0; i < n_in; ++i) {
        if (in_sizes[i] == K_TOPICS * VOCAB)      beta  = (const float*)d_in[i];
        else if (in_sizes[i] == VOCAB * VOCAB)    W     = (const float*)d_in[i];
        else if (in_sizes[i] == 1)                epoch = (const int*)d_in[i];
    }
    float* out = (float*)d_out;

    zero_kernel<<<(VOCAB + 255) / 256, 256>>>();
    topk_kernel<<<K_TOPICS, 256>>>(beta);
    loss_kernel<<<K_TOPICS, 1024>>>(beta, W);
    finalize_kernel<<<1, 1>>>(epoch, out);
}

// round 3
// speedup vs baseline: 1.2661x; 1.2661x over previous
#include <cuda_runtime.h>
#include <cuda_bf16.h>
#include <float.h>
#include <math.h>

#define K_TOPICS 100
#define VOCAB    8192
#define TOPN     20
#define NTHREADS 1024

// ---- persistent device scratch (zero-initialized at module load) ----
__device__ int   g_topidx[K_TOPICS * TOPN];
__device__ int   g_arrive;     // monotone ticket counter (barrier)
__device__ int   g_done;       // monotone ticket counter (finalize)
__device__ float g_pos;
__device__ float g_neg;

__device__ __forceinline__ int ld_acquire(const int* p) {
    int v;
    asm volatile("ld.global.acquire.gpu.b32 %0, [%1];" : "=r"(v) : "l"(p) : "memory");
    return v;
}

// ----------------------------------------------------------------------------
// ONE fused persistent kernel. grid = 100 (one CTA per topic), 1024 threads.
// Thread tid owns 8 columns: {4*tid+k} and {4096+4*tid+k}, k=0..3 (coalesced).
// Phases:
//   A) rowmax + softmax denom + exact top-20 (register-cached argmax)
//   B) write own top-20 to global, ARRIVE at grid barrier (no wait yet)
//   C) M = p @ W gather (DRAM-bound, hides barrier skew), row min/max
//   D) WAIT barrier, build "other-topic" bitmap, per-column loss, reduce
//   E) last CTA finalizes the scalar and resets accumulators
// ----------------------------------------------------------------------------
__global__ void __launch_bounds__(NTHREADS)
fused_kernel(const float* __restrict__ beta, const float* __restrict__ W,
             const int* __restrict__ epoch_ptr, float* __restrict__ out) {
    const int t   = blockIdx.x;
    const int tid = threadIdx.x;
    const int lane = tid & 31;
    const int wid  = tid >> 5;

    __shared__ float s_wval[32];
    __shared__ int   s_wind[32];
    __shared__ float s_red[32];
    __shared__ float s_bc0, s_bc1;
    __shared__ int   s_win;
    __shared__ float s_topv[TOPN];
    __shared__ int   s_topi[TOPN];
    __shared__ float s_p[TOPN];
    __shared__ unsigned s_bm[VOCAB / 32];   // 1 KB bitmap
    __shared__ int   s_ticket;

    const float4* __restrict__ beta4 = (const float4*)(beta + (size_t)t * VOCAB);
    float4 b0 = beta4[tid];          // cols 4*tid   .. +3
    float4 b1 = beta4[tid + 1024];   // cols 4096+4*tid .. +3

    // ---------- phase A: rowmax ----------
    float m = fmaxf(fmaxf(fmaxf(b0.x, b0.y), fmaxf(b0.z, b0.w)),
                    fmaxf(fmaxf(b1.x, b1.y), fmaxf(b1.z, b1.w)));
    for (int o = 16; o > 0; o >>= 1) m = fmaxf(m, __shfl_xor_sync(~0u, m, o));
    if (lane == 0) s_red[wid] = m;
    __syncthreads();
    if (tid < 32) {
        float v = s_red[tid];
        for (int o = 16; o > 0; o >>= 1) v = fmaxf(v, __shfl_xor_sync(~0u, v, o));
        if (tid == 0) s_bc0 = v;
    }
    __syncthreads();
    const float rowmax = s_bc0;

    // ---------- full-row softmax denom ----------
    float z = expf(b0.x - rowmax) + expf(b0.y - rowmax) + expf(b0.z - rowmax) + expf(b0.w - rowmax)
            + expf(b1.x - rowmax) + expf(b1.y - rowmax) + expf(b1.z - rowmax) + expf(b1.w - rowmax);
    for (int o = 16; o > 0; o >>= 1) z += __shfl_xor_sync(~0u, z, o);
    if (lane == 0) s_red[wid] = z;
    __syncthreads();
    if (tid < 32) {
        float v = s_red[tid];
        for (int o = 16; o > 0; o >>= 1) v += __shfl_xor_sync(~0u, v, o);
        if (tid == 0) s_bc1 = v;
    }
    __syncthreads();
    const float invden = 1.0f / s_bc1;

    // ---------- exact top-20, register-cached local argmax ----------
    unsigned mask = 0xFFu;       // which of my 8 elements are still live
    float lv; int li;
    {   // initial local best
        lv = -FLT_MAX; li = -1;
        const float vs[8] = { b0.x, b0.y, b0.z, b0.w, b1.x, b1.y, b1.z, b1.w };
        #pragma unroll
        for (int k = 0; k < 8; ++k) {
            int col = (k < 4) ? (4 * tid + k) : (4096 + 4 * tid + (k - 4));
            if (vs[k] > lv) { lv = vs[k]; li = col; }
        }
    }

    for (int it = 0; it < TOPN; ++it) {
        float v = lv; int idx = li;
        for (int o = 16; o > 0; o >>= 1) {
            float ov = __shfl_xor_sync(~0u, v, o);
            int   oi = __shfl_xor_sync(~0u, idx, o);
            if (ov > v || (ov == v && oi < idx)) { v = ov; idx = oi; }
        }
        if (lane == 0) { s_wval[wid] = v; s_wind[wid] = idx; }
        __syncthreads();
        if (tid < 32) {
            float vv = s_wval[tid]; int ii = s_wind[tid];
            for (int o = 16; o > 0; o >>= 1) {
                float ov = __shfl_xor_sync(~0u, vv, o);
                int   oi = __shfl_xor_sync(~0u, ii, o);
                if (ov > vv || (ov == vv && oi < ii)) { vv = ov; ii = oi; }
            }
            if (tid == 0) { s_topv[it] = vv; s_topi[it] = ii; s_win = ii; }
        }
        __syncthreads();
        const int win = s_win;
        if (li == win) {     // I owned the winner: knock out + rescan my 8
            int k = (win < 4096) ? (win - 4 * tid) : (4 + (win - 4096 - 4 * tid));
            mask &= ~(1u << k);
            lv = -FLT_MAX; li = -1;
            const float vs[8] = { b0.x, b0.y, b0.z, b0.w, b1.x, b1.y, b1.z, b1.w };
            #pragma unroll
            for (int kk = 0; kk < 8; ++kk) {
                int col = (kk < 4) ? (4 * tid + kk) : (4096 + 4 * tid + (kk - 4));
                if ((mask >> kk) & 1u) {
                    if (vs[kk] > lv) { lv = vs[kk]; li = col; }
                }
            }
        }
        __syncthreads();
    }

    // ---------- p over top-20, publish indices ----------
    if (tid == 0) {
        float zz = 0.0f;
        for (int j = 0; j < TOPN; ++j) zz += expf(s_topv[j] - rowmax);
        float pinv = 1.0f / zz;
        for (int j = 0; j < TOPN; ++j) s_p[j] = expf(s_topv[j] - rowmax) * pinv;
    }
    if (tid < TOPN) g_topidx[t * TOPN + tid] = s_topi[tid];
    __syncthreads();

    // ---------- phase B: ARRIVE (release), don't wait yet ----------
    if (tid == 0) {
        __threadfence();
        int ticket = atomicAdd(&g_arrive, 1);
        s_ticket = ((ticket / K_TOPICS) + 1) * K_TOPICS;  // target for this replay
    }
    __syncthreads();
    const int target = s_ticket;

    // ---------- phase C: M = p @ W  (DRAM-bound; hides barrier skew) ----------
    const float4* __restrict__ W4 = (const float4*)W;
    float4 acc0 = make_float4(0.f, 0.f, 0.f, 0.f);
    float4 acc1 = make_float4(0.f, 0.f, 0.f, 0.f);
    #pragma unroll 5
    for (int j = 0; j < TOPN; ++j) {
        const size_t base = (size_t)s_topi[j] * (VOCAB / 4);
        const float  w    = s_p[j];
        float4 a = __ldg(&W4[base + tid]);
        float4 b = __ldg(&W4[base + tid + 1024]);
        acc0.x += w * a.x; acc0.y += w * a.y; acc0.z += w * a.z; acc0.w += w * a.w;
        acc1.x += w * b.x; acc1.y += w * b.y; acc1.z += w * b.z; acc1.w += w * b.w;
    }

    // ---------- row min/max of M ----------
    float mn = fminf(fminf(fminf(acc0.x, acc0.y), fminf(acc0.z, acc0.w)),
                     fminf(fminf(acc1.x, acc1.y), fminf(acc1.z, acc1.w)));
    float mx = fmaxf(fmaxf(fmaxf(acc0.x, acc0.y), fmaxf(acc0.z, acc0.w)),
                     fmaxf(fmaxf(acc1.x, acc1.y), fmaxf(acc1.z, acc1.w)));
    for (int o = 16; o > 0; o >>= 1) {
        mn = fminf(mn, __shfl_xor_sync(~0u, mn, o));
        mx = fmaxf(mx, __shfl_xor_sync(~0u, mx, o));
    }
    if (lane == 0) { s_wval[wid] = mn; s_red[wid] = mx; }
    __syncthreads();
    if (tid < 32) {
        float a = s_wval[tid], b = s_red[tid];
        for (int o = 16; o > 0; o >>= 1) {
            a = fminf(a, __shfl_xor_sync(~0u, a, o));
            b = fmaxf(b, __shfl_xor_sync(~0u, b, o));
        }
        if (tid == 0) { s_bc0 = a; s_bc1 = b; }
    }
    __syncthreads();
    const float mmin = s_bc0;
    const float minv = 1.0f / (s_bc1 - mmin);

    // ---------- phase D: WAIT barrier, build other-topic bitmap ----------
    if (tid == 0) {
        while (ld_acquire(&g_arrive) < target) __nanosleep(64);
    }
    if (tid < VOCAB / 32) s_bm[tid] = 0u;
    __syncthreads();

    for (int e = tid; e < K_TOPICS * TOPN; e += NTHREADS) {
        int j = e / TOPN;
        if (j != t) {
            int idx;
            asm volatile("ld.global.cg.b32 %0, [%1];" : "=r"(idx) : "l"(&g_topidx[e]));
            atomicOr(&s_bm[idx >> 5], 1u << (idx & 31));
        }
    }
    __syncthreads();

    // ---------- per-column loss ----------
    float pos = 0.0f, neg = 0.0f;
    {
        const float bb[8] = { b0.x, b0.y, b0.z, b0.w, b1.x, b1.y, b1.z, b1.w };
        const float MM[8] = { acc0.x, acc0.y, acc0.z, acc0.w, acc1.x, acc1.y, acc1.z, acc1.w };
        #pragma unroll
        for (int k = 0; k < 8; ++k) {
            int col = (k < 4) ? (4 * tid + k) : (4096 + 4 * tid + (k - 4));
            float sft = expf(bb[k] - rowmax) * invden;
            float wc  = 1.0f - (MM[k] - mmin) * minv;
            float l   = 100.0f * sft * sft * wc;
            bool  md  = (s_bm[col >> 5] >> (col & 31)) & 1u;
            if (md) pos += l; else neg += l;
        }
    }
    for (int o = 16; o > 0; o >>= 1) {
        pos += __shfl_xor_sync(~0u, pos, o);
        neg += __shfl_xor_sync(~0u, neg, o);
    }
    if (lane == 0) { s_wval[wid] = pos; s_red[wid] = neg; }
    __syncthreads();
    if (tid == 0) {
        float P = 0.0f, N = 0.0f;
        #pragma unroll
        for (int w = 0; w < 32; ++w) { P += s_wval[w]; N += s_red[w]; }
        atomicAdd(&g_pos, P);
        atomicAdd(&g_neg, N);
        __threadfence();
        int t2 = atomicAdd(&g_done, 1);
        if ((t2 % K_TOPICS) == K_TOPICS - 1) {
            // phase E: last CTA of this replay — finalize & reset
            float gp = atomicAdd(&g_pos, 0.0f);   // RMW: serialized with all adds
            float gn = atomicAdd(&g_neg, 0.0f);
            const int   epoch    = epoch_ptr[0];
            const int   warmup   = 100;           // 0.5 * 200
            const float lambda_a = (epoch < warmup) ? (float)epoch : 100.0f;
            out[0] = lambda_a * (gp * 0.7f + gn * 0.3f) * 2.0f;
            g_pos = 0.0f;
            g_neg = 0.0f;
            __threadfence();
        }
    }
}

// ----------------------------------------------------------------------------
extern "C" void kernel_launch(void* const* d_in, const int* in_sizes, int n_in,
                              void* d_out, int out_size) {
    const float* beta  = nullptr;
    const float* W     = nullptr;
    const int*   epoch = nullptr;
    for (int i = 0; i < n_in; ++i) {
        if (in_sizes[i] == K_TOPICS * VOCAB)   beta  = (const float*)d_in[i];
        else if (in_sizes[i] == VOCAB * VOCAB) W     = (const float*)d_in[i];
        else if (in_sizes[i] == 1)             epoch = (const int*)d_in[i];
    }
    fused_kernel<<<K_TOPICS, NTHREADS>>>(beta, W, epoch, (float*)d_out);
}

// round 6
// speedup vs baseline: 1.4818x; 1.1703x over previous
#include <cuda_runtime.h>
#include <cuda_bf16.h>
#include <float.h>
#include <math.h>

#define K_TOPICS 100
#define VOCAB    8192
#define TOPN     20
#define NT       512
#define CPT      2                    // CTAs per topic
#define NCTA     (K_TOPICS * CPT)     // 200

// ---- persistent device scratch (zero-initialized at module load) ----
__device__ int   g_topidx[K_TOPICS * TOPN];
__device__ float g_mn[NCTA];
__device__ float g_mx[NCTA];
__device__ int   g_arrive;     // monotone ticket (grid barrier)
__device__ int   g_done;       // monotone ticket (finalize)
__device__ float g_pos;
__device__ float g_neg;

__device__ __forceinline__ int ld_acquire(const int* p) {
    int v;
    asm volatile("ld.global.acquire.gpu.b32 %0, [%1];" : "=r"(v) : "l"(p) : "memory");
    return v;
}
__device__ __forceinline__ float ldcg_f(const float* p) {
    float v;
    asm volatile("ld.global.cg.f32 %0, [%1];" : "=f"(v) : "l"(p) : "memory");
    return v;
}
__device__ __forceinline__ int ldcg_i(const int* p) {
    int v;
    asm volatile("ld.global.cg.b32 %0, [%1];" : "=r"(v) : "l"(p) : "memory");
    return v;
}
// order-preserving float->u32 key: larger float => larger key
__device__ __forceinline__ unsigned fkey(float f) {
    unsigned b = __float_as_uint(f);
    return (b & 0x80000000u) ? ~b : (b | 0x80000000u);
}

// ----------------------------------------------------------------------------
// grid = 200 (2 CTAs per topic), block = 512.
// CTA (t = bid/2, half = bid&1) owns columns [half*4096, half*4096+4096).
// ----------------------------------------------------------------------------
__global__ void __launch_bounds__(NT, 2)
fused_kernel(const float* __restrict__ beta, const float* __restrict__ W,
             const int* __restrict__ epoch_ptr, float* __restrict__ out) {
    const int bid  = blockIdx.x;
    const int t    = bid >> 1;
    const int half = bid & 1;
    const int tid  = threadIdx.x;
    const int lane = tid & 31;
    const int wid  = tid >> 5;

    __shared__ unsigned s_hist[256];
    __shared__ unsigned s_selbyte;
    __shared__ unsigned s_above;
    __shared__ int      s_cnt;
    __shared__ float    s_cv[128];
    __shared__ int      s_ci[128];
    __shared__ float    s_topv[TOPN];
    __shared__ int      s_topi[TOPN];
    __shared__ float    s_p[TOPN];
    __shared__ float    s_r0[NT / 32];
    __shared__ float    s_r1[NT / 32];
    __shared__ float    s_f0, s_f1;
    __shared__ unsigned s_bm[VOCAB / 32];   // 1 KB

    // ---- load full beta row: 16 values/thread as 4 float4 ----
    const float4* __restrict__ beta4 = (const float4*)(beta + (size_t)t * VOCAB);
    float4 r[4];
    #pragma unroll
    for (int q = 0; q < 4; ++q) r[q] = beta4[tid + NT * q];

    // =========== exact top-20 via rank-aware 3-pass radix select ===========
    // Invariant entering pass p: the current bucket (keys matching `pref`)
    // contains >= `want` keys, and the global rank-20 key is the bucket's
    // rank-`want` key. Each pass narrows the prefix by 8 bits.
    unsigned pref = 0;
    unsigned want = TOPN;
    #pragma unroll
    for (int pass = 0; pass < 3; ++pass) {
        const int shift = 24 - 8 * pass;
        if (tid < 256) s_hist[tid] = 0u;
        __syncthreads();
        #pragma unroll
        for (int q = 0; q < 4; ++q) {
            const float vv[4] = { r[q].x, r[q].y, r[q].z, r[q].w };
            #pragma unroll
            for (int k = 0; k < 4; ++k) {
                unsigned key = fkey(vv[k]);
                bool ok = (pass == 0) || ((key >> (shift + 8)) == pref);
                if (ok) atomicAdd(&s_hist[(key >> shift) & 0xFFu], 1u);
            }
        }
        __syncthreads();
        if (tid < 32) {
            const unsigned w = want;          // uniform across block
            unsigned c[8], s = 0;
            #pragma unroll
            for (int i = 0; i < 8; ++i) { c[i] = s_hist[lane * 8 + i]; s += c[i]; }
            unsigned run = s;                 // suffix-sum over lanes >= lane
            #pragma unroll
            for (int o = 1; o < 32; o <<= 1) {
                unsigned v = __shfl_down_sync(~0u, run, o);
                if (lane + o < 32) run += v;
            }
            unsigned cum = run - s;           // keys in bins strictly above my group
            #pragma unroll
            for (int i = 7; i >= 0; --i) {    // descending: cum = keys above bin i
                if (cum < w && cum + c[i] >= w) {
                    s_selbyte = (unsigned)(lane * 8 + i);
                    s_above   = cum;          // keys above the selected bin
                }
                cum += c[i];
            }
        }
        __syncthreads();
        pref = (pref << 8) | s_selbyte;
        want -= s_above;                      // rank within the new bucket
        __syncthreads();
    }

    // ---- compact candidates with 24-bit key prefix >= threshold prefix ----
    // Superset of the exact top-20 (keys above final bin + final bin), ~20-25.
    if (tid == 0) s_cnt = 0;
    __syncthreads();
    #pragma unroll
    for (int q = 0; q < 4; ++q) {
        const float vv[4] = { r[q].x, r[q].y, r[q].z, r[q].w };
        #pragma unroll
        for (int k = 0; k < 4; ++k) {
            unsigned key = fkey(vv[k]);
            if ((key >> 8) >= pref) {
                int p = atomicAdd(&s_cnt, 1);
                if (p < 128) { s_cv[p] = vv[k]; s_ci[p] = 4 * (tid + NT * q) + k; }
            }
        }
    }
    __syncthreads();

    // ---- warp 0: exact top-20 among candidates ----
    if (tid < 32) {
        const int C = min(s_cnt, 128);
        float cv[4]; int ci[4];
        #pragma unroll
        for (int s = 0; s < 4; ++s) {
            int p = lane + 32 * s;
            cv[s] = (p < C) ? s_cv[p] : -FLT_MAX;
            ci[s] = (p < C) ? s_ci[p] : (VOCAB - 1);
        }
        float bv = -FLT_MAX; int bi = VOCAB - 1;
        #pragma unroll
        for (int s = 0; s < 4; ++s) if (cv[s] > bv) { bv = cv[s]; bi = ci[s]; }
        for (int it = 0; it < TOPN; ++it) {
            float v = bv; int i = bi;
            #pragma unroll
            for (int o = 16; o > 0; o >>= 1) {
                float ov = __shfl_xor_sync(~0u, v, o);
                int   oi = __shfl_xor_sync(~0u, i, o);
                if (ov > v || (ov == v && oi < i)) { v = ov; i = oi; }
            }
            if (lane == 0) { s_topv[it] = v; s_topi[it] = i; }
            if (bi == i) {                    // I own the winner: knock out
                #pragma unroll
                for (int s = 0; s < 4; ++s) if (ci[s] == i) cv[s] = -FLT_MAX;
                bv = -FLT_MAX; bi = VOCAB - 1;
                #pragma unroll
                for (int s = 0; s < 4; ++s) if (cv[s] > bv) { bv = cv[s]; bi = ci[s]; }
            }
            __syncwarp();
        }
        if (lane == 0) {
            const float rowmax = s_topv[0];
            float zz = 0.0f;
            for (int j = 0; j < TOPN; ++j) zz += expf(s_topv[j] - rowmax);
            float pinv = 1.0f / zz;
            for (int j = 0; j < TOPN; ++j) s_p[j] = expf(s_topv[j] - rowmax) * pinv;
        }
    }
    __syncthreads();
    const float rowmax = s_topv[0];

    // ---- full-row softmax denominator ----
    float z = 0.0f;
    #pragma unroll
    for (int q = 0; q < 4; ++q)
        z += expf(r[q].x - rowmax) + expf(r[q].y - rowmax)
           + expf(r[q].z - rowmax) + expf(r[q].w - rowmax);
    for (int o = 16; o > 0; o >>= 1) z += __shfl_xor_sync(~0u, z, o);
    if (lane == 0) s_r0[wid] = z;
    __syncthreads();
    if (tid == 0) {
        float v = 0.0f;
        #pragma unroll
        for (int w = 0; w < NT / 32; ++w) v += s_r0[w];
        s_f0 = 1.0f / v;
    }
    // publish own top-20 (only one CTA per topic writes)
    if (half == 0 && tid < TOPN) g_topidx[t * TOPN + tid] = s_topi[tid];
    __syncthreads();
    const float invden = s_f0;

    // keep this CTA's loss columns in registers
    const float4 bl = r[2 * half];       // cols 4096*half + 4*tid   .. +3
    const float4 bh = r[2 * half + 1];   // cols 4096*half + 2048 + 4*tid .. +3

    // =========== gather: M = p @ W over this CTA's half-row ===========
    const float4* __restrict__ W4 = (const float4*)W;
    const int hbase = half * 1024;       // float4 offset of this half
    float4 acc0 = make_float4(0.f, 0.f, 0.f, 0.f);
    float4 acc1 = make_float4(0.f, 0.f, 0.f, 0.f);
    #pragma unroll 5
    for (int j = 0; j < TOPN; ++j) {
        const int   rowi = s_topi[j] & (VOCAB - 1);   // defense: never OOB
        const size_t base = (size_t)rowi * (VOCAB / 4) + hbase;
        const float  w    = s_p[j];
        float4 a = __ldg(&W4[base + tid]);
        float4 b = __ldg(&W4[base + tid + NT]);
        acc0.x += w * a.x; acc0.y += w * a.y; acc0.z += w * a.z; acc0.w += w * a.w;
        acc1.x += w * b.x; acc1.y += w * b.y; acc1.z += w * b.z; acc1.w += w * b.w;
    }

    // ---- partial min/max of M over this half ----
    float mn = fminf(fminf(fminf(acc0.x, acc0.y), fminf(acc0.z, acc0.w)),
                     fminf(fminf(acc1.x, acc1.y), fminf(acc1.z, acc1.w)));
    float mx = fmaxf(fmaxf(fmaxf(acc0.x, acc0.y), fmaxf(acc0.z, acc0.w)),
                     fmaxf(fmaxf(acc1.x, acc1.y), fmaxf(acc1.z, acc1.w)));
    for (int o = 16; o > 0; o >>= 1) {
        mn = fminf(mn, __shfl_xor_sync(~0u, mn, o));
        mx = fmaxf(mx, __shfl_xor_sync(~0u, mx, o));
    }
    if (lane == 0) { s_r0[wid] = mn; s_r1[wid] = mx; }
    __syncthreads();
    if (tid == 0) {
        float a = FLT_MAX, b = -FLT_MAX;
        #pragma unroll
        for (int w = 0; w < NT / 32; ++w) { a = fminf(a, s_r0[w]); b = fmaxf(b, s_r1[w]); }
        // publish partials, arrive at grid barrier, spin
        g_mn[bid] = a;
        g_mx[bid] = b;
        __threadfence();
        int ticket = atomicAdd(&g_arrive, 1);
        int target = ((ticket / NCTA) + 1) * NCTA;
        while (ld_acquire(&g_arrive) < target) __nanosleep(32);
    }
    if (tid < VOCAB / 32) s_bm[tid] = 0u;
    __syncthreads();   // holds everyone until tid0 passes the grid barrier

    // ---- combined min/max + "other topic" bitmap ----
    if (tid == 0) {
        s_f0 = fminf(ldcg_f(&g_mn[t * 2]), ldcg_f(&g_mn[t * 2 + 1]));
        s_f1 = fmaxf(ldcg_f(&g_mx[t * 2]), ldcg_f(&g_mx[t * 2 + 1]));
    }
    for (int e = tid; e < K_TOPICS * TOPN; e += NT) {
        if ((e / TOPN) != t) {
            int idx = ldcg_i(&g_topidx[e]) & (VOCAB - 1);
            atomicOr(&s_bm[idx >> 5], 1u << (idx & 31));
        }
    }
    __syncthreads();
    const float mmin = s_f0;
    const float minv = 1.0f / (s_f1 - mmin);

    // ---- per-column loss over this CTA's 8 columns/thread ----
    float pos = 0.0f, neg = 0.0f;
    {
        const float bb[8] = { bl.x, bl.y, bl.z, bl.w, bh.x, bh.y, bh.z, bh.w };
        const float MM[8] = { acc0.x, acc0.y, acc0.z, acc0.w, acc1.x, acc1.y, acc1.z, acc1.w };
        #pragma unroll
        for (int k = 0; k < 8; ++k) {
            int col = 4096 * half + ((k < 4) ? (4 * tid + k) : (2048 + 4 * tid + (k - 4)));
            float sft = expf(bb[k] - rowmax) * invden;
            float wc  = 1.0f - (MM[k] - mmin) * minv;
            float l   = 100.0f * sft * sft * wc;
            bool  md  = (s_bm[col >> 5] >> (col & 31)) & 1u;
            if (md) pos += l; else neg += l;
        }
    }
    for (int o = 16; o > 0; o >>= 1) {
        pos += __shfl_xor_sync(~0u, pos, o);
        neg += __shfl_xor_sync(~0u, neg, o);
    }
    if (lane == 0) { s_r0[wid] = pos; s_r1[wid] = neg; }
    __syncthreads();
    if (tid == 0) {
        float P = 0.0f, N = 0.0f;
        #pragma unroll
        for (int w = 0; w < NT / 32; ++w) { P += s_r0[w]; N += s_r1[w]; }
        atomicAdd(&g_pos, P);
        atomicAdd(&g_neg, N);
        __threadfence();
        int t2 = atomicAdd(&g_done, 1);
        if ((t2 % NCTA) == NCTA - 1) {       // last CTA of this replay
            float gp = atomicAdd(&g_pos, 0.0f);
            float gn = atomicAdd(&g_neg, 0.0f);
            const int   epoch    = epoch_ptr[0];
            const float lambda_a = (epoch < 100) ? (float)epoch : 100.0f;
            out[0] = lambda_a * (gp * 0.7f + gn * 0.3f) * 2.0f;
            g_pos = 0.0f;
            g_neg = 0.0f;
            __threadfence();
        }
    }
}

// ----------------------------------------------------------------------------
extern "C" void kernel_launch(void* const* d_in, const int* in_sizes, int n_in,
                              void* d_out, int out_size) {
    const float* beta  = nullptr;
    const float* W     = nullptr;
    const int*   epoch = nullptr;
    for (int i = 0; i < n_in; ++i) {
        if (in_sizes[i] == K_TOPICS * VOCAB)   beta  = (const float*)d_in[i];
        else if (in_sizes[i] == VOCAB * VOCAB) W     = (const float*)d_in[i];
        else if (in_sizes[i] == 1)             epoch = (const int*)d_in[i];
    }
    fused_kernel<<<NCTA, NT>>>(beta, W, epoch, (float*)d_out);
}